// round 10
// baseline (speedup 1.0000x reference)
#include <cuda_runtime.h>
#include <math.h>
#include <stdint.h>

#define DIM     768
#define NH      12
#define HD      64
#define HIDDEN  3072
#define SEQ     2048
#define BATCH   4
#define TOKENS  (BATCH*SEQ)   // 8192
#define EPS     1e-6f

// ---------------- scratch (static device globals; no allocations) -----------
__device__ float g_h    [(size_t)TOKENS * DIM];
__device__ float g_qkv  [(size_t)TOKENS * 3 * DIM];
__device__ float g_attn [(size_t)TOKENS * DIM];
__device__ float g_x1   [(size_t)TOKENS * DIM];
__device__ float g_h2   [(size_t)TOKENS * HIDDEN];

extern __shared__ float dynsm[];

__device__ __forceinline__ float gelu_exact(float x) {
    return 0.5f * x * (1.0f + erff(x * 0.70710678118654752440f));
}

__device__ __forceinline__ float ex2a(float x) {
    float y;
    asm("ex2.approx.ftz.f32 %0, %1;" : "=f"(y) : "f"(x));
    return y;
}

__device__ __forceinline__ void mma_tf32(float* c, const uint32_t* a, const uint32_t* b) {
    asm volatile(
        "mma.sync.aligned.m16n8k8.row.col.f32.tf32.tf32.f32 "
        "{%0,%1,%2,%3}, {%4,%5,%6,%7}, {%8,%9}, {%0,%1,%2,%3};"
        : "+f"(c[0]), "+f"(c[1]), "+f"(c[2]), "+f"(c[3])
        : "r"(a[0]), "r"(a[1]), "r"(a[2]), "r"(a[3]), "r"(b[0]), "r"(b[1]));
}

__device__ __forceinline__ void cp16(float* s, const float* g) {
    uint32_t sa = (uint32_t)__cvta_generic_to_shared(s);
    asm volatile("cp.async.cg.shared.global [%0], [%1], 16;" :: "r"(sa), "l"(g));
}

// ---------------- LayerNorm: one warp per token ------------------------------
__global__ void ln_kernel(const float* __restrict__ x, const float* __restrict__ g,
                          const float* __restrict__ b, float* __restrict__ out) {
    int lane = threadIdx.x & 31, warp = threadIdx.x >> 5;
    long t = (long)blockIdx.x * 8 + warp;
    const float* xr = x + t * DIM;
    float4 v[6];
    float s = 0.f;
    #pragma unroll
    for (int i = 0; i < 6; i++) {
        v[i] = *(const float4*)&xr[(i * 32 + lane) * 4];
        s += v[i].x + v[i].y + v[i].z + v[i].w;
    }
    #pragma unroll
    for (int o = 16; o; o >>= 1) s += __shfl_xor_sync(0xffffffffu, s, o);
    float mu = s * (1.0f / DIM);
    float q = 0.f;
    #pragma unroll
    for (int i = 0; i < 6; i++) {
        v[i].x -= mu; v[i].y -= mu; v[i].z -= mu; v[i].w -= mu;
        q += v[i].x*v[i].x + v[i].y*v[i].y + v[i].z*v[i].z + v[i].w*v[i].w;
    }
    #pragma unroll
    for (int o = 16; o; o >>= 1) q += __shfl_xor_sync(0xffffffffu, q, o);
    float rinv = rsqrtf(q * (1.0f / DIM) + EPS);
    float* orow = out + t * DIM;
    #pragma unroll
    for (int i = 0; i < 6; i++) {
        int idx = (i * 32 + lane) * 4;
        float4 gg = *(const float4*)&g[idx];
        float4 bb = *(const float4*)&b[idx];
        float4 o4;
        o4.x = v[i].x * rinv * gg.x + bb.x;
        o4.y = v[i].y * rinv * gg.y + bb.y;
        o4.z = v[i].z * rinv * gg.z + bb.z;
        o4.w = v[i].w * rinv * gg.w + bb.w;
        *(float4*)&orow[idx] = o4;
    }
}

// ================== Flash attention (R8 version, unchanged) ==================
#define FA_BR   128
#define FA_BC   64
#define FA_NIT  (SEQ / FA_BC)          // 32
#define QS_STR  68
#define KS_STR  68
#define VS_STR  72
#define KS_BUF  (FA_BC * KS_STR)
#define VS_BUF  (FA_BC * VS_STR)
#define FA_SMEM_FLOATS (FA_BR*QS_STR + 2*KS_BUF + 2*VS_BUF)
#define FA_SMEM_BYTES  (FA_SMEM_FLOATS * 4)   // 106,496 B -> 2 CTAs/SM

__global__ void __launch_bounds__(256, 2) flash_kernel(
    const float* __restrict__ qkv, float* __restrict__ attn)
{
    float* Qs = dynsm;
    float* Ks = Qs + FA_BR * QS_STR;
    float* Vs = Ks + 2 * KS_BUF;

    int tid  = threadIdx.x, lane = tid & 31, warp = tid >> 5;
    int r4 = lane >> 2, l4 = lane & 3;
    int bh = blockIdx.y, bb = bh / NH, hh = bh % NH;
    long base = (long)bb * SEQ * (3 * DIM) + hh * HD;
    const float* Qg = qkv + base + (long)blockIdx.x * FA_BR * (3 * DIM);
    const float* Kg = qkv + base + DIM;
    const float* Vg = qkv + base + 2 * DIM;

    #pragma unroll
    for (int t = 0; t < 8; t++) {
        int id = tid + t * 256; int r = id >> 4, c = (id & 15) * 4;
        cp16(&Qs[r * QS_STR + c], Qg + (long)r * (3 * DIM) + c);
    }
    asm volatile("cp.async.commit_group;\n");

    #pragma unroll
    for (int t = 0; t < 4; t++) {
        int id = tid + t * 256; int r = id >> 4, c = (id & 15) * 4;
        int rv = (r & ~7) | (((r & 3) << 1) | ((r >> 2) & 1));
        cp16(&Ks[r * KS_STR + c], Kg + (long)r * (3 * DIM) + c);
        cp16(&Vs[r * VS_STR + c], Vg + (long)rv * (3 * DIM) + c);
    }
    asm volatile("cp.async.commit_group;\n");

    float accO[8][4];
    #pragma unroll
    for (int ni = 0; ni < 8; ni++)
        #pragma unroll
        for (int r = 0; r < 4; r++) accO[ni][r] = 0.f;
    float mrun[2] = {-INFINITY, -INFINITY};
    float lrun[2] = {0.f, 0.f};
    const float fscale = 0.125f * 1.44269504f;
    int m0 = warp * 16 + r4;

    for (int j = 0; j < FA_NIT; j++) {
        float* Kb = Ks + (j & 1) * KS_BUF;
        float* Vb = Vs + (j & 1) * VS_BUF;

        asm volatile("cp.async.wait_group 0;\n" ::: "memory");
        __syncthreads();

        if (j + 1 < FA_NIT) {
            int nb = (j + 1) & 1;
            const float* Kn = Kg + (long)(j + 1) * FA_BC * (3 * DIM);
            const float* Vn = Vg + (long)(j + 1) * FA_BC * (3 * DIM);
            #pragma unroll
            for (int t = 0; t < 4; t++) {
                int id = tid + t * 256; int r = id >> 4, c = (id & 15) * 4;
                int rv = (r & ~7) | (((r & 3) << 1) | ((r >> 2) & 1));
                cp16(&Ks[nb * KS_BUF + r * KS_STR + c], Kn + (long)r * (3 * DIM) + c);
                cp16(&Vs[nb * VS_BUF + r * VS_STR + c], Vn + (long)rv * (3 * DIM) + c);
            }
            asm volatile("cp.async.commit_group;\n");
        }

        float accS[8][4];
        #pragma unroll
        for (int ni = 0; ni < 8; ni++)
            #pragma unroll
            for (int r = 0; r < 4; r++) accS[ni][r] = 0.f;
        #pragma unroll
        for (int ks = 0; ks < 8; ks++) {
            int kb = ks * 8 + l4;
            uint32_t af[4];
            af[0] = __float_as_uint(Qs[m0 * QS_STR + kb]);
            af[1] = __float_as_uint(Qs[(m0 + 8) * QS_STR + kb]);
            af[2] = __float_as_uint(Qs[m0 * QS_STR + kb + 4]);
            af[3] = __float_as_uint(Qs[(m0 + 8) * QS_STR + kb + 4]);
            uint32_t bfr[8][2];
            #pragma unroll
            for (int ni = 0; ni < 8; ni++) {
                int n = ni * 8 + r4;
                bfr[ni][0] = __float_as_uint(Kb[n * KS_STR + kb]);
                bfr[ni][1] = __float_as_uint(Kb[n * KS_STR + kb + 4]);
            }
            #pragma unroll
            for (int ni = 0; ni < 8; ni++)
                mma_tf32(accS[ni], af, bfr[ni]);
        }
        #pragma unroll
        for (int ni = 0; ni < 8; ni++)
            #pragma unroll
            for (int r = 0; r < 4; r++) accS[ni][r] *= fscale;

        #pragma unroll
        for (int h = 0; h < 2; h++) {
            float tm = -INFINITY;
            #pragma unroll
            for (int ni = 0; ni < 8; ni++)
                tm = fmaxf(tm, fmaxf(accS[ni][2*h], accS[ni][2*h + 1]));
            tm = fmaxf(tm, __shfl_xor_sync(0xffffffffu, tm, 1));
            tm = fmaxf(tm, __shfl_xor_sync(0xffffffffu, tm, 2));
            float mn = fmaxf(mrun[h], tm);
            float alpha = ex2a(mrun[h] - mn);
            mrun[h] = mn;
            float ps = 0.f;
            #pragma unroll
            for (int ni = 0; ni < 8; ni++) {
                float p0 = ex2a(accS[ni][2*h]     - mn);
                float p1 = ex2a(accS[ni][2*h + 1] - mn);
                ps += p0 + p1;
                accS[ni][2*h] = p0; accS[ni][2*h + 1] = p1;
            }
            ps += __shfl_xor_sync(0xffffffffu, ps, 1);
            ps += __shfl_xor_sync(0xffffffffu, ps, 2);
            lrun[h] = lrun[h] * alpha + ps;
            #pragma unroll
            for (int ni = 0; ni < 8; ni++) {
                accO[ni][2*h]     *= alpha;
                accO[ni][2*h + 1] *= alpha;
            }
        }

        #pragma unroll
        for (int ks = 0; ks < 8; ks++) {
            uint32_t a[4];
            a[0] = __float_as_uint(accS[ks][0]);
            a[1] = __float_as_uint(accS[ks][2]);
            a[2] = __float_as_uint(accS[ks][1]);
            a[3] = __float_as_uint(accS[ks][3]);
            uint32_t bfr[8][2];
            #pragma unroll
            for (int ni = 0; ni < 8; ni++) {
                bfr[ni][0] = __float_as_uint(Vb[(ks * 8 + l4)     * VS_STR + ni * 8 + r4]);
                bfr[ni][1] = __float_as_uint(Vb[(ks * 8 + l4 + 4) * VS_STR + ni * 8 + r4]);
            }
            #pragma unroll
            for (int ni = 0; ni < 8; ni++)
                mma_tf32(accO[ni], a, bfr[ni]);
        }
    }

    float* orow_base = attn + ((long)bb * SEQ + (long)blockIdx.x * FA_BR) * DIM + hh * HD;
    #pragma unroll
    for (int h = 0; h < 2; h++) {
        float inv = 1.0f / lrun[h];
        int row = warp * 16 + r4 + 8 * h;
        float* orow = orow_base + (long)row * DIM;
        #pragma unroll
        for (int ni = 0; ni < 8; ni++) {
            *(float2*)&orow[ni * 8 + 2 * l4] =
                make_float2(accO[ni][2*h] * inv, accO[ni][2*h + 1] * inv);
        }
    }
}

// ---------------- TF32 GEMM: 256x128 CTA tile, 64x64 warp tiles -------------
// C[m,n] = sum_k A[m,k] * B[n,k]  (+bias[n]) (gelu) (+res[m,n])
// 256 threads = 4(m) x 2(n) warps; warp tile 64x64 (MT=4, NT=8): per k8 step
// 32 LDS vs 32 mma (ratio 1.0 vs 1.5 at warp 32x64) -> less crossbar pressure.
// 3-stage cp.async pipeline, BK=32, smem stride 36 (conflict-free frag LDS).
// acc = 128 regs/thread; launch_bounds(256) (1 CTA/SM, 255 regs available).
#define GM_STR    36
#define GM_BK     32
#define GM_ASTG   (256 * GM_STR)           // A floats per stage
#define GM_BSTG   (128 * GM_STR)           // B floats per stage
#define GM_SMEM_BYTES (3 * (GM_ASTG + GM_BSTG) * 4)   // 165,888 B

__global__ void __launch_bounds__(256) gemm_tf32_kernel(
    const float* __restrict__ A, int lda,
    const float* __restrict__ B, int ldb,
    float* __restrict__ C, int ldc,
    const float* __restrict__ bias, const float* __restrict__ res,
    int K, int gelu)
{
    float* As = dynsm;                 // [3][256][GM_STR]
    float* Bs = dynsm + 3 * GM_ASTG;   // [3][128][GM_STR]

    int tid    = threadIdx.x;
    int lane   = tid & 31;
    int warp   = tid >> 5;
    int warp_m = warp >> 1;            // 0..3 -> 64-row strip
    int warp_n = warp & 1;             // 0..1 -> 64-col strip
    int r4 = lane >> 2, l4 = lane & 3;
    int row0   = blockIdx.y * 256;
    int col0   = blockIdx.x * 128;

    const float* Ab = A + (long)row0 * lda;
    const float* Bb = B + (long)col0 * ldb;

    int nt = K / GM_BK;

    // load maps: A 256x32 -> 8 cp16/thread; B 128x32 -> 4 cp16/thread
    int ar[8], ac[8], br[4], bc[4];
    #pragma unroll
    for (int t = 0; t < 8; t++) { int id = tid + t * 256; ar[t] = id >> 3; ac[t] = (id & 7) * 4; }
    #pragma unroll
    for (int t = 0; t < 4; t++) { int id = tid + t * 256; br[t] = id >> 3; bc[t] = (id & 7) * 4; }

    // prologue: stages 0 and 1 (nt >= 2 always: K >= 768)
    #pragma unroll
    for (int s = 0; s < 2; s++) {
        int k0 = s * GM_BK;
        #pragma unroll
        for (int t = 0; t < 8; t++)
            cp16(&As[(s * 256 + ar[t]) * GM_STR + ac[t]], Ab + (long)ar[t] * lda + k0 + ac[t]);
        #pragma unroll
        for (int t = 0; t < 4; t++)
            cp16(&Bs[(s * 128 + br[t]) * GM_STR + bc[t]], Bb + (long)br[t] * ldb + k0 + bc[t]);
        asm volatile("cp.async.commit_group;\n");
    }

    float acc[4][8][4];
    #pragma unroll
    for (int mi = 0; mi < 4; mi++)
        #pragma unroll
        for (int ni = 0; ni < 8; ni++)
            #pragma unroll
            for (int r = 0; r < 4; r++) acc[mi][ni][r] = 0.f;

    int stage = 0, nstage = 2;
    for (int j = 0; j < nt; j++) {
        if (j + 1 < nt) asm volatile("cp.async.wait_group 1;\n" ::: "memory");
        else            asm volatile("cp.async.wait_group 0;\n" ::: "memory");
        __syncthreads();

        if (j + 2 < nt) {
            int k0 = (j + 2) * GM_BK;
            #pragma unroll
            for (int t = 0; t < 8; t++)
                cp16(&As[(nstage * 256 + ar[t]) * GM_STR + ac[t]],
                     Ab + (long)ar[t] * lda + k0 + ac[t]);
            #pragma unroll
            for (int t = 0; t < 4; t++)
                cp16(&Bs[(nstage * 128 + br[t]) * GM_STR + bc[t]],
                     Bb + (long)br[t] * ldb + k0 + bc[t]);
            asm volatile("cp.async.commit_group;\n");
        }
        nstage = nstage + 1 == 3 ? 0 : nstage + 1;

        const float* Asb = As + stage * GM_ASTG;
        const float* Bsb = Bs + stage * GM_BSTG;
        stage = stage + 1 == 3 ? 0 : stage + 1;

        #pragma unroll
        for (int ks = 0; ks < 4; ks++) {
            int kb = ks * 8 + l4;
            uint32_t af[4][4];
            #pragma unroll
            for (int mi = 0; mi < 4; mi++) {
                int r = warp_m * 64 + mi * 16 + r4;
                af[mi][0] = __float_as_uint(Asb[r * GM_STR + kb]);
                af[mi][1] = __float_as_uint(Asb[(r + 8) * GM_STR + kb]);
                af[mi][2] = __float_as_uint(Asb[r * GM_STR + kb + 4]);
                af[mi][3] = __float_as_uint(Asb[(r + 8) * GM_STR + kb + 4]);
            }
            uint32_t bf[8][2];
            #pragma unroll
            for (int ni = 0; ni < 8; ni++) {
                int c = warp_n * 64 + ni * 8 + r4;
                bf[ni][0] = __float_as_uint(Bsb[c * GM_STR + kb]);
                bf[ni][1] = __float_as_uint(Bsb[c * GM_STR + kb + 4]);
            }
            #pragma unroll
            for (int mi = 0; mi < 4; mi++)
                #pragma unroll
                for (int ni = 0; ni < 8; ni++)
                    mma_tf32(acc[mi][ni], af[mi], bf[ni]);
        }
    }

    // epilogue
    #pragma unroll
    for (int mi = 0; mi < 4; mi++) {
        #pragma unroll
        for (int half = 0; half < 2; half++) {
            int row = row0 + warp_m * 64 + mi * 16 + r4 + half * 8;
            float* crow = C + (long)row * ldc;
            const float* rrow = res ? res + (long)row * ldc : (const float*)0;
            #pragma unroll
            for (int ni = 0; ni < 8; ni++) {
                int col = col0 + warp_n * 64 + ni * 8 + l4 * 2;
                float v0 = acc[mi][ni][half * 2 + 0];
                float v1 = acc[mi][ni][half * 2 + 1];
                if (bias) { v0 += bias[col]; v1 += bias[col + 1]; }
                if (gelu) { v0 = gelu_exact(v0); v1 = gelu_exact(v1); }
                if (res)  { float2 rr = *(const float2*)&rrow[col]; v0 += rr.x; v1 += rr.y; }
                *(float2*)&crow[col] = make_float2(v0, v1);
            }
        }
    }
}

// ---------------- launch ----------------------------------------------------
extern "C" void kernel_launch(void* const* d_in, const int* in_sizes, int n_in,
                              void* d_out, int out_size) {
    const float* x      = (const float*)d_in[0];
    const float* ln1_g  = (const float*)d_in[1];
    const float* ln1_b  = (const float*)d_in[2];
    const float* qkv_w  = (const float*)d_in[3];
    const float* qkv_b  = (const float*)d_in[4];
    const float* proj_w = (const float*)d_in[5];
    const float* proj_b = (const float*)d_in[6];
    const float* ln2_g  = (const float*)d_in[7];
    const float* ln2_b  = (const float*)d_in[8];
    const float* fc1_w  = (const float*)d_in[9];
    const float* fc1_b  = (const float*)d_in[10];
    const float* fc2_w  = (const float*)d_in[11];
    const float* fc2_b  = (const float*)d_in[12];
    float* out = (float*)d_out;

    float *h, *qkv, *attn, *x1, *h2;
    cudaGetSymbolAddress((void**)&h,    g_h);
    cudaGetSymbolAddress((void**)&qkv,  g_qkv);
    cudaGetSymbolAddress((void**)&attn, g_attn);
    cudaGetSymbolAddress((void**)&x1,   g_x1);
    cudaGetSymbolAddress((void**)&h2,   g_h2);

    cudaFuncSetAttribute(flash_kernel,
                         cudaFuncAttributeMaxDynamicSharedMemorySize, FA_SMEM_BYTES);
    cudaFuncSetAttribute(gemm_tf32_kernel,
                         cudaFuncAttributeMaxDynamicSharedMemorySize, GM_SMEM_BYTES);

    // 1. LN1
    ln_kernel<<<TOKENS / 8, 256>>>(x, ln1_g, ln1_b, h);

    // 2. QKV = h @ qkv_w^T + qkv_b      [8192 x 2304], K=768
    gemm_tf32_kernel<<<dim3(3 * DIM / 128, TOKENS / 256), 256, GM_SMEM_BYTES>>>(
        h, DIM, qkv_w, DIM, qkv, 3 * DIM, qkv_b, nullptr, DIM, 0);

    // 3-5. fused flash attention -> attn [token][DIM]
    flash_kernel<<<dim3(SEQ / FA_BR, BATCH * NH), 256, FA_SMEM_BYTES>>>(qkv, attn);

    // 6. x1 = x + attn @ proj_w^T + proj_b
    gemm_tf32_kernel<<<dim3(DIM / 128, TOKENS / 256), 256, GM_SMEM_BYTES>>>(
        attn, DIM, proj_w, DIM, x1, DIM, proj_b, x, DIM, 0);

    // 7. LN2
    ln_kernel<<<TOKENS / 8, 256>>>(x1, ln2_g, ln2_b, h);

    // 8. h2 = gelu(h @ fc1_w^T + fc1_b)   [8192 x 3072], K=768
    gemm_tf32_kernel<<<dim3(HIDDEN / 128, TOKENS / 256), 256, GM_SMEM_BYTES>>>(
        h, DIM, fc1_w, DIM, h2, HIDDEN, fc1_b, nullptr, DIM, 1);

    // 9. out = x1 + h2 @ fc2_w^T + fc2_b  [8192 x 768], K=3072
    gemm_tf32_kernel<<<dim3(DIM / 128, TOKENS / 256), 256, GM_SMEM_BYTES>>>(
        h2, HIDDEN, fc2_w, HIDDEN, out, DIM, fc2_b, x1, HIDDEN, 0);
}

// round 13
// speedup vs baseline: 1.1278x; 1.1278x over previous
#include <cuda_runtime.h>
#include <math.h>
#include <stdint.h>

#define DIM     768
#define NH      12
#define HD      64
#define HIDDEN  3072
#define SEQ     2048
#define BATCH   4
#define TOKENS  (BATCH*SEQ)   // 8192
#define EPS     1e-6f
#define MN_OUT  ((size_t)TOKENS * DIM)   // 6.29M elems per fc2 slab

// ---------------- scratch (static device globals; no allocations) -----------
__device__ float g_h    [(size_t)TOKENS * DIM];
__device__ float g_qkv  [(size_t)TOKENS * 3 * DIM];
__device__ float g_attn [(size_t)TOKENS * DIM];
__device__ float g_x1   [(size_t)TOKENS * DIM];
__device__ float g_h2   [(size_t)TOKENS * HIDDEN];
__device__ float g_part [(size_t)4 * TOKENS * DIM];   // split-K partials, 100MB

extern __shared__ float dynsm[];

__device__ __forceinline__ float gelu_exact(float x) {
    return 0.5f * x * (1.0f + erff(x * 0.70710678118654752440f));
}

__device__ __forceinline__ float ex2a(float x) {
    float y;
    asm("ex2.approx.ftz.f32 %0, %1;" : "=f"(y) : "f"(x));
    return y;
}

__device__ __forceinline__ void mma_tf32(float* c, const uint32_t* a, const uint32_t* b) {
    asm volatile(
        "mma.sync.aligned.m16n8k8.row.col.f32.tf32.tf32.f32 "
        "{%0,%1,%2,%3}, {%4,%5,%6,%7}, {%8,%9}, {%0,%1,%2,%3};"
        : "+f"(c[0]), "+f"(c[1]), "+f"(c[2]), "+f"(c[3])
        : "r"(a[0]), "r"(a[1]), "r"(a[2]), "r"(a[3]), "r"(b[0]), "r"(b[1]));
}

__device__ __forceinline__ void cp16(float* s, const float* g) {
    uint32_t sa = (uint32_t)__cvta_generic_to_shared(s);
    asm volatile("cp.async.cg.shared.global [%0], [%1], 16;" :: "r"(sa), "l"(g));
}

// ---------------- LayerNorm: one warp per token ------------------------------
__global__ void ln_kernel(const float* __restrict__ x, const float* __restrict__ g,
                          const float* __restrict__ b, float* __restrict__ out) {
    int lane = threadIdx.x & 31, warp = threadIdx.x >> 5;
    long t = (long)blockIdx.x * 8 + warp;
    const float* xr = x + t * DIM;
    float4 v[6];
    float s = 0.f;
    #pragma unroll
    for (int i = 0; i < 6; i++) {
        v[i] = *(const float4*)&xr[(i * 32 + lane) * 4];
        s += v[i].x + v[i].y + v[i].z + v[i].w;
    }
    #pragma unroll
    for (int o = 16; o; o >>= 1) s += __shfl_xor_sync(0xffffffffu, s, o);
    float mu = s * (1.0f / DIM);
    float q = 0.f;
    #pragma unroll
    for (int i = 0; i < 6; i++) {
        v[i].x -= mu; v[i].y -= mu; v[i].z -= mu; v[i].w -= mu;
        q += v[i].x*v[i].x + v[i].y*v[i].y + v[i].z*v[i].z + v[i].w*v[i].w;
    }
    #pragma unroll
    for (int o = 16; o; o >>= 1) q += __shfl_xor_sync(0xffffffffu, q, o);
    float rinv = rsqrtf(q * (1.0f / DIM) + EPS);
    float* orow = out + t * DIM;
    #pragma unroll
    for (int i = 0; i < 6; i++) {
        int idx = (i * 32 + lane) * 4;
        float4 gg = *(const float4*)&g[idx];
        float4 bb = *(const float4*)&b[idx];
        float4 o4;
        o4.x = v[i].x * rinv * gg.x + bb.x;
        o4.y = v[i].y * rinv * gg.y + bb.y;
        o4.z = v[i].z * rinv * gg.z + bb.z;
        o4.w = v[i].w * rinv * gg.w + bb.w;
        *(float4*)&orow[idx] = o4;
    }
}

// ---------------- split-K reduce: out = res + sum4(part) + bias --------------
__global__ void reduce4_kernel(const float* __restrict__ part,
                               const float* __restrict__ bias,
                               const float* __restrict__ res,
                               float* __restrict__ out) {
    size_t i = ((size_t)blockIdx.x * 256 + threadIdx.x) * 4;
    int col = (int)(i % DIM);
    float4 a = *(const float4*)&part[i];
    float4 b = *(const float4*)&part[i + MN_OUT];
    float4 c = *(const float4*)&part[i + 2 * MN_OUT];
    float4 d = *(const float4*)&part[i + 3 * MN_OUT];
    float4 bb = *(const float4*)&bias[col];
    float4 rr = *(const float4*)&res[i];
    float4 o;
    o.x = rr.x + bb.x + ((a.x + b.x) + (c.x + d.x));
    o.y = rr.y + bb.y + ((a.y + b.y) + (c.y + d.y));
    o.z = rr.z + bb.z + ((a.z + b.z) + (c.z + d.z));
    o.w = rr.w + bb.w + ((a.w + b.w) + (c.w + d.w));
    *(float4*)&out[i] = o;
}

// ================== Flash attention (R8 version, unchanged) ==================
#define FA_BR   128
#define FA_BC   64
#define FA_NIT  (SEQ / FA_BC)          // 32
#define QS_STR  68
#define KS_STR  68
#define VS_STR  72
#define KS_BUF  (FA_BC * KS_STR)
#define VS_BUF  (FA_BC * VS_STR)
#define FA_SMEM_FLOATS (FA_BR*QS_STR + 2*KS_BUF + 2*VS_BUF)
#define FA_SMEM_BYTES  (FA_SMEM_FLOATS * 4)   // 106,496 B -> 2 CTAs/SM

__global__ void __launch_bounds__(256, 2) flash_kernel(
    const float* __restrict__ qkv, float* __restrict__ attn)
{
    float* Qs = dynsm;
    float* Ks = Qs + FA_BR * QS_STR;
    float* Vs = Ks + 2 * KS_BUF;

    int tid  = threadIdx.x, lane = tid & 31, warp = tid >> 5;
    int r4 = lane >> 2, l4 = lane & 3;
    int bh = blockIdx.y, bb = bh / NH, hh = bh % NH;
    long base = (long)bb * SEQ * (3 * DIM) + hh * HD;
    const float* Qg = qkv + base + (long)blockIdx.x * FA_BR * (3 * DIM);
    const float* Kg = qkv + base + DIM;
    const float* Vg = qkv + base + 2 * DIM;

    #pragma unroll
    for (int t = 0; t < 8; t++) {
        int id = tid + t * 256; int r = id >> 4, c = (id & 15) * 4;
        cp16(&Qs[r * QS_STR + c], Qg + (long)r * (3 * DIM) + c);
    }
    asm volatile("cp.async.commit_group;\n");

    #pragma unroll
    for (int t = 0; t < 4; t++) {
        int id = tid + t * 256; int r = id >> 4, c = (id & 15) * 4;
        int rv = (r & ~7) | (((r & 3) << 1) | ((r >> 2) & 1));
        cp16(&Ks[r * KS_STR + c], Kg + (long)r * (3 * DIM) + c);
        cp16(&Vs[r * VS_STR + c], Vg + (long)rv * (3 * DIM) + c);
    }
    asm volatile("cp.async.commit_group;\n");

    float accO[8][4];
    #pragma unroll
    for (int ni = 0; ni < 8; ni++)
        #pragma unroll
        for (int r = 0; r < 4; r++) accO[ni][r] = 0.f;
    float mrun[2] = {-INFINITY, -INFINITY};
    float lrun[2] = {0.f, 0.f};
    const float fscale = 0.125f * 1.44269504f;
    int m0 = warp * 16 + r4;

    for (int j = 0; j < FA_NIT; j++) {
        float* Kb = Ks + (j & 1) * KS_BUF;
        float* Vb = Vs + (j & 1) * VS_BUF;

        asm volatile("cp.async.wait_group 0;\n" ::: "memory");
        __syncthreads();

        if (j + 1 < FA_NIT) {
            int nb = (j + 1) & 1;
            const float* Kn = Kg + (long)(j + 1) * FA_BC * (3 * DIM);
            const float* Vn = Vg + (long)(j + 1) * FA_BC * (3 * DIM);
            #pragma unroll
            for (int t = 0; t < 4; t++) {
                int id = tid + t * 256; int r = id >> 4, c = (id & 15) * 4;
                int rv = (r & ~7) | (((r & 3) << 1) | ((r >> 2) & 1));
                cp16(&Ks[nb * KS_BUF + r * KS_STR + c], Kn + (long)r * (3 * DIM) + c);
                cp16(&Vs[nb * VS_BUF + r * VS_STR + c], Vn + (long)rv * (3 * DIM) + c);
            }
            asm volatile("cp.async.commit_group;\n");
        }

        float accS[8][4];
        #pragma unroll
        for (int ni = 0; ni < 8; ni++)
            #pragma unroll
            for (int r = 0; r < 4; r++) accS[ni][r] = 0.f;
        #pragma unroll
        for (int ks = 0; ks < 8; ks++) {
            int kb = ks * 8 + l4;
            uint32_t af[4];
            af[0] = __float_as_uint(Qs[m0 * QS_STR + kb]);
            af[1] = __float_as_uint(Qs[(m0 + 8) * QS_STR + kb]);
            af[2] = __float_as_uint(Qs[m0 * QS_STR + kb + 4]);
            af[3] = __float_as_uint(Qs[(m0 + 8) * QS_STR + kb + 4]);
            uint32_t bfr[8][2];
            #pragma unroll
            for (int ni = 0; ni < 8; ni++) {
                int n = ni * 8 + r4;
                bfr[ni][0] = __float_as_uint(Kb[n * KS_STR + kb]);
                bfr[ni][1] = __float_as_uint(Kb[n * KS_STR + kb + 4]);
            }
            #pragma unroll
            for (int ni = 0; ni < 8; ni++)
                mma_tf32(accS[ni], af, bfr[ni]);
        }
        #pragma unroll
        for (int ni = 0; ni < 8; ni++)
            #pragma unroll
            for (int r = 0; r < 4; r++) accS[ni][r] *= fscale;

        #pragma unroll
        for (int h = 0; h < 2; h++) {
            float tm = -INFINITY;
            #pragma unroll
            for (int ni = 0; ni < 8; ni++)
                tm = fmaxf(tm, fmaxf(accS[ni][2*h], accS[ni][2*h + 1]));
            tm = fmaxf(tm, __shfl_xor_sync(0xffffffffu, tm, 1));
            tm = fmaxf(tm, __shfl_xor_sync(0xffffffffu, tm, 2));
            float mn = fmaxf(mrun[h], tm);
            float alpha = ex2a(mrun[h] - mn);
            mrun[h] = mn;
            float ps = 0.f;
            #pragma unroll
            for (int ni = 0; ni < 8; ni++) {
                float p0 = ex2a(accS[ni][2*h]     - mn);
                float p1 = ex2a(accS[ni][2*h + 1] - mn);
                ps += p0 + p1;
                accS[ni][2*h] = p0; accS[ni][2*h + 1] = p1;
            }
            ps += __shfl_xor_sync(0xffffffffu, ps, 1);
            ps += __shfl_xor_sync(0xffffffffu, ps, 2);
            lrun[h] = lrun[h] * alpha + ps;
            #pragma unroll
            for (int ni = 0; ni < 8; ni++) {
                accO[ni][2*h]     *= alpha;
                accO[ni][2*h + 1] *= alpha;
            }
        }

        #pragma unroll
        for (int ks = 0; ks < 8; ks++) {
            uint32_t a[4];
            a[0] = __float_as_uint(accS[ks][0]);
            a[1] = __float_as_uint(accS[ks][2]);
            a[2] = __float_as_uint(accS[ks][1]);
            a[3] = __float_as_uint(accS[ks][3]);
            uint32_t bfr[8][2];
            #pragma unroll
            for (int ni = 0; ni < 8; ni++) {
                bfr[ni][0] = __float_as_uint(Vb[(ks * 8 + l4)     * VS_STR + ni * 8 + r4]);
                bfr[ni][1] = __float_as_uint(Vb[(ks * 8 + l4 + 4) * VS_STR + ni * 8 + r4]);
            }
            #pragma unroll
            for (int ni = 0; ni < 8; ni++)
                mma_tf32(accO[ni], a, bfr[ni]);
        }
    }

    float* orow_base = attn + ((long)bb * SEQ + (long)blockIdx.x * FA_BR) * DIM + hh * HD;
    #pragma unroll
    for (int h = 0; h < 2; h++) {
        float inv = 1.0f / lrun[h];
        int row = warp * 16 + r4 + 8 * h;
        float* orow = orow_base + (long)row * DIM;
        #pragma unroll
        for (int ni = 0; ni < 8; ni++) {
            *(float2*)&orow[ni * 8 + 2 * l4] =
                make_float2(accO[ni][2*h] * inv, accO[ni][2*h + 1] * inv);
        }
    }
}

// ---------------- TF32 GEMM: R8 config + optional split-K --------------------
// C[m,n] = sum_k A[m,k+kOff] * B[n,k+kOff]  where kOff = blockIdx.z * K.
// If part != null: raw partials to part + z*MN_OUT (bias/gelu/res skipped).
// Tile 128x128xBK32, 256 threads = 4(m) x 2(n) warps, warp 32x64.
// 3-stage cp.async pipeline, smem stride 36, one barrier per K-tile.
#define GM_STR   36
#define GM_BK    32
#define GM_STAGE (128 * GM_STR)
#define GM_SMEM_BYTES (6 * GM_STAGE * 4)        // 110,592 B -> 2 CTAs/SM

__global__ void __launch_bounds__(256, 2) gemm_tf32_kernel(
    const float* __restrict__ A, int lda,
    const float* __restrict__ B, int ldb,
    float* __restrict__ C, int ldc,
    const float* __restrict__ bias, const float* __restrict__ res,
    int K, int gelu, float* __restrict__ part)
{
    float* As = dynsm;                 // [3][128][GM_STR]
    float* Bs = dynsm + 3 * GM_STAGE;  // [3][128][GM_STR]

    int tid    = threadIdx.x;
    int lane   = tid & 31;
    int warp   = tid >> 5;
    int warp_m = warp >> 1;
    int warp_n = warp & 1;
    int r4 = lane >> 2, l4 = lane & 3;
    int row0   = blockIdx.y * 128;
    int col0   = blockIdx.x * 128;
    long kOff  = (long)blockIdx.z * K;

    const float* Ab = A + (long)row0 * lda + kOff;
    const float* Bb = B + (long)col0 * ldb + kOff;

    int nt = K / GM_BK;

    int lrow[4], lc4[4];
    #pragma unroll
    for (int t = 0; t < 4; t++) {
        int c = tid + t * 256;
        lrow[t] = c >> 3;
        lc4[t]  = (c & 7) * 4;
    }

    // prologue: stages 0 and 1
    #pragma unroll
    for (int t = 0; t < 4; t++) {
        cp16(&As[lrow[t] * GM_STR + lc4[t]], Ab + (long)lrow[t] * lda + lc4[t]);
        cp16(&Bs[lrow[t] * GM_STR + lc4[t]], Bb + (long)lrow[t] * ldb + lc4[t]);
    }
    asm volatile("cp.async.commit_group;\n");
    #pragma unroll
    for (int t = 0; t < 4; t++) {
        cp16(&As[(128 + lrow[t]) * GM_STR + lc4[t]], Ab + (long)lrow[t] * lda + GM_BK + lc4[t]);
        cp16(&Bs[(128 + lrow[t]) * GM_STR + lc4[t]], Bb + (long)lrow[t] * ldb + GM_BK + lc4[t]);
    }
    asm volatile("cp.async.commit_group;\n");

    float acc[2][8][4];
    #pragma unroll
    for (int mi = 0; mi < 2; mi++)
        #pragma unroll
        for (int ni = 0; ni < 8; ni++)
            #pragma unroll
            for (int r = 0; r < 4; r++) acc[mi][ni][r] = 0.f;

    int stage = 0, nstage = 2;
    for (int j = 0; j < nt; j++) {
        if (j + 1 < nt) asm volatile("cp.async.wait_group 1;\n" ::: "memory");
        else            asm volatile("cp.async.wait_group 0;\n" ::: "memory");
        __syncthreads();

        if (j + 2 < nt) {
            int k0 = (j + 2) * GM_BK;
            #pragma unroll
            for (int t = 0; t < 4; t++) {
                cp16(&As[(nstage * 128 + lrow[t]) * GM_STR + lc4[t]],
                     Ab + (long)lrow[t] * lda + k0 + lc4[t]);
                cp16(&Bs[(nstage * 128 + lrow[t]) * GM_STR + lc4[t]],
                     Bb + (long)lrow[t] * ldb + k0 + lc4[t]);
            }
            asm volatile("cp.async.commit_group;\n");
        }
        nstage = nstage + 1 == 3 ? 0 : nstage + 1;

        const float* Asb = As + stage * GM_STAGE;
        const float* Bsb = Bs + stage * GM_STAGE;
        stage = stage + 1 == 3 ? 0 : stage + 1;

        #pragma unroll
        for (int ks = 0; ks < 4; ks++) {
            int kb = ks * 8 + l4;
            uint32_t af[2][4];
            #pragma unroll
            for (int mi = 0; mi < 2; mi++) {
                int r = warp_m * 32 + mi * 16 + r4;
                af[mi][0] = __float_as_uint(Asb[r * GM_STR + kb]);
                af[mi][1] = __float_as_uint(Asb[(r + 8) * GM_STR + kb]);
                af[mi][2] = __float_as_uint(Asb[r * GM_STR + kb + 4]);
                af[mi][3] = __float_as_uint(Asb[(r + 8) * GM_STR + kb + 4]);
            }
            uint32_t bf[8][2];
            #pragma unroll
            for (int ni = 0; ni < 8; ni++) {
                int c = warp_n * 64 + ni * 8 + r4;
                bf[ni][0] = __float_as_uint(Bsb[c * GM_STR + kb]);
                bf[ni][1] = __float_as_uint(Bsb[c * GM_STR + kb + 4]);
            }
            #pragma unroll
            for (int mi = 0; mi < 2; mi++)
                #pragma unroll
                for (int ni = 0; ni < 8; ni++)
                    mma_tf32(acc[mi][ni], af[mi], bf[ni]);
        }
    }

    // epilogue
    float* Cout = part ? part + (size_t)blockIdx.z * MN_OUT : C;
    #pragma unroll
    for (int mi = 0; mi < 2; mi++) {
        #pragma unroll
        for (int half = 0; half < 2; half++) {
            int row = row0 + warp_m * 32 + mi * 16 + r4 + half * 8;
            float* crow = Cout + (long)row * ldc;
            const float* rrow = res ? res + (long)row * ldc : (const float*)0;
            #pragma unroll
            for (int ni = 0; ni < 8; ni++) {
                int col = col0 + warp_n * 64 + ni * 8 + l4 * 2;
                float v0 = acc[mi][ni][half * 2 + 0];
                float v1 = acc[mi][ni][half * 2 + 1];
                if (!part) {
                    if (bias) { v0 += bias[col]; v1 += bias[col + 1]; }
                    if (gelu) { v0 = gelu_exact(v0); v1 = gelu_exact(v1); }
                    if (res)  { float2 rr = *(const float2*)&rrow[col]; v0 += rr.x; v1 += rr.y; }
                }
                *(float2*)&crow[col] = make_float2(v0, v1);
            }
        }
    }
}

// ---------------- launch ----------------------------------------------------
extern "C" void kernel_launch(void* const* d_in, const int* in_sizes, int n_in,
                              void* d_out, int out_size) {
    const float* x      = (const float*)d_in[0];
    const float* ln1_g  = (const float*)d_in[1];
    const float* ln1_b  = (const float*)d_in[2];
    const float* qkv_w  = (const float*)d_in[3];
    const float* qkv_b  = (const float*)d_in[4];
    const float* proj_w = (const float*)d_in[5];
    const float* proj_b = (const float*)d_in[6];
    const float* ln2_g  = (const float*)d_in[7];
    const float* ln2_b  = (const float*)d_in[8];
    const float* fc1_w  = (const float*)d_in[9];
    const float* fc1_b  = (const float*)d_in[10];
    const float* fc2_w  = (const float*)d_in[11];
    const float* fc2_b  = (const float*)d_in[12];
    float* out = (float*)d_out;

    float *h, *qkv, *attn, *x1, *h2, *part;
    cudaGetSymbolAddress((void**)&h,    g_h);
    cudaGetSymbolAddress((void**)&qkv,  g_qkv);
    cudaGetSymbolAddress((void**)&attn, g_attn);
    cudaGetSymbolAddress((void**)&x1,   g_x1);
    cudaGetSymbolAddress((void**)&h2,   g_h2);
    cudaGetSymbolAddress((void**)&part, g_part);

    cudaFuncSetAttribute(flash_kernel,
                         cudaFuncAttributeMaxDynamicSharedMemorySize, FA_SMEM_BYTES);
    cudaFuncSetAttribute(gemm_tf32_kernel,
                         cudaFuncAttributeMaxDynamicSharedMemorySize, GM_SMEM_BYTES);

    // 1. LN1
    ln_kernel<<<TOKENS / 8, 256>>>(x, ln1_g, ln1_b, h);

    // 2. QKV = h @ qkv_w^T + qkv_b      [8192 x 2304], K=768
    gemm_tf32_kernel<<<dim3(3 * DIM / 128, TOKENS / 128), 256, GM_SMEM_BYTES>>>(
        h, DIM, qkv_w, DIM, qkv, 3 * DIM, qkv_b, nullptr, DIM, 0, nullptr);

    // 3-5. fused flash attention -> attn [token][DIM]
    flash_kernel<<<dim3(SEQ / FA_BR, BATCH * NH), 256, FA_SMEM_BYTES>>>(qkv, attn);

    // 6. x1 = x + attn @ proj_w^T + proj_b
    gemm_tf32_kernel<<<dim3(DIM / 128, TOKENS / 128), 256, GM_SMEM_BYTES>>>(
        attn, DIM, proj_w, DIM, x1, DIM, proj_b, x, DIM, 0, nullptr);

    // 7. LN2
    ln_kernel<<<TOKENS / 8, 256>>>(x1, ln2_g, ln2_b, h);

    // 8. h2 = gelu(h @ fc1_w^T + fc1_b)   [8192 x 3072], K=768
    gemm_tf32_kernel<<<dim3(HIDDEN / 128, TOKENS / 128), 256, GM_SMEM_BYTES>>>(
        h, DIM, fc1_w, DIM, h2, HIDDEN, fc1_b, nullptr, DIM, 1, nullptr);

    // 9a. split-K=4 partials: part[z] = h2[:, z*768:(z+1)*768] @ fc2_w[:, z*768:..]^T
    gemm_tf32_kernel<<<dim3(DIM / 128, TOKENS / 128, 4), 256, GM_SMEM_BYTES>>>(
        h2, HIDDEN, fc2_w, HIDDEN, nullptr, DIM, nullptr, nullptr, HIDDEN / 4, 0, part);

    // 9b. out = x1 + sum_z part[z] + fc2_b
    reduce4_kernel<<<(int)(MN_OUT / 4 / 256), 256>>>(part, fc2_b, x1, out);
}